// round 3
// baseline (speedup 1.0000x reference)
#include <cuda_runtime.h>

#define NN 8192
#define NE 16384
#define W  512
#define NS (NE / W)          // 32 strips
#define GRID 148
#define TPB 1024
#define KMAX 7               // ceil(56 rows / 8 teams)

// ---- scratch (device globals; no allocation allowed) ----
__device__ float g_u[NN];
__device__ float g_v[NN];
__device__ float g_c[NN];
__device__ float g_ai[NE];
__device__ float g_ao[NE];
__device__ float g_part[2][GRID][2 * W];   // [slot][cta][which*512+col]
__device__ int   g_doneA[NS];
__device__ int   g_fin[NS];

__device__ __forceinline__ int ld_acq(const int* p) {
    int v;
    asm volatile("ld.acquire.gpu.s32 %0, [%1];" : "=r"(v) : "l"(p) : "memory");
    return v;
}
__device__ __forceinline__ void f4add(float4& a, const float4 b) {
    a.x += b.x; a.y += b.y; a.z += b.z; a.w += b.w;
}
__device__ __forceinline__ void f4fma(float4& a, const float4 b, float s) {
    a.x += b.x * s; a.y += b.y * s; a.z += b.z * s; a.w += b.w * s;
}

// Prep: per-node scalars u=X·k1, v=X·k2, c=X·k3; reset sync counters.
__global__ void k1_prep(const float* __restrict__ X, const float* __restrict__ kw) {
    int n = blockIdx.x * blockDim.x + threadIdx.x;
    if (n < NS) { g_doneA[n] = 0; g_fin[n] = 0; }
    if (n >= NN) return;
    float4 x = reinterpret_cast<const float4*>(X)[n];
    g_u[n] = x.x * kw[0] + x.y * kw[1] + x.z * kw[2]  + x.w * kw[3];
    g_v[n] = x.x * kw[4] + x.y * kw[5] + x.z * kw[6]  + x.w * kw[7];
    g_c[n] = x.x * kw[8] + x.y * kw[9] + x.z * kw[10] + x.w * kw[11];
}

// Fused persistent kernel: every CTA does BOTH the DRAM col-reduce of strip s
// and the L2-hit row-reduce of strip s-1 in one interleaved loop.
__global__ __launch_bounds__(TPB, 1) void fused(const float* __restrict__ Ri,
                                                const float* __restrict__ Ro,
                                                const float* __restrict__ ew,
                                                float* __restrict__ out) {
    __shared__ float4 sA[TPB];          // 16 KB: ai partial tree
    __shared__ float4 sB[TPB];          // 16 KB: ao partial tree
    __shared__ float4 s_ai[W / 4];      // 2 KB
    __shared__ float4 s_ao[W / 4];      // 2 KB
    __shared__ float  spu[64], spv[64];
    __shared__ float  sred[8][4];

    const int t    = threadIdx.x;
    const int cta  = blockIdx.x;
    const int team = t >> 7;            // 0..7
    const int lane = t & 127;           // float4 col group within strip
    const int r0 = (int)(((long long)cta * NN) / GRID);
    const int r1 = (int)(((long long)(cta + 1) * NN) / GRID);
    const int nrows = r1 - r0;          // 55 or 56

    if (t < nrows) { spu[t] = g_u[r0 + t]; spv[t] = g_v[r0 + t]; }

    float accB[KMAX];
#pragma unroll
    for (int k = 0; k < KMAX; ++k) accB[k] = 0.f;
    __syncthreads();

    for (int s = 0; s <= NS; ++s) {
        const bool haveA = (s < NS);
        const bool haveB = (s > 0);

        float4 vai = make_float4(0.f, 0.f, 0.f, 0.f);
        float4 vao = make_float4(0.f, 0.f, 0.f, 0.f);
        if (haveB) {
            if (t == 0) { while (ld_acq(&g_fin[s - 1]) < GRID) __nanosleep(32); }
            __syncthreads();
            if (t < 128)
                s_ai[t] = *reinterpret_cast<const float4*>(&g_ai[(s - 1) * W + t * 4]);
            else if (t < 256)
                s_ao[t - 128] = *reinterpret_cast<const float4*>(&g_ao[(s - 1) * W + (t - 128) * 4]);
            __syncthreads();
            vai = s_ai[lane];
            vao = s_ao[lane];
        }

        float4 pai = make_float4(0.f, 0.f, 0.f, 0.f);
        float4 pao = make_float4(0.f, 0.f, 0.f, 0.f);
        const size_t colA = (size_t)s * W + lane * 4;

#pragma unroll
        for (int k = 0; k < KMAX; ++k) {
            const int rr = team + k * 8;
            if (rr < nrows) {
                const float* bi = Ri + (size_t)(r0 + rr) * NE;
                const float* bo = Ro + (size_t)(r0 + rr) * NE;
                if (haveA) {                       // DRAM leg: strip s
                    const float4 a = *reinterpret_cast<const float4*>(bi + colA);
                    const float4 b = *reinterpret_cast<const float4*>(bo + colA);
                    f4fma(pai, b, spu[rr]);        // ai += Ro * u
                    f4fma(pao, a, spv[rr]);        // ao += Ri * v
                }
                if (haveB) {                       // L2 leg: strip s-1
                    const float4 a = *reinterpret_cast<const float4*>(bi + colA - W);
                    const float4 b = *reinterpret_cast<const float4*>(bo + colA - W);
                    accB[k] += a.x * vai.x + a.y * vai.y + a.z * vai.z + a.w * vai.w
                             + b.x * vao.x + b.y * vao.y + b.z * vao.z + b.w * vao.w;
                }
            }
        }

        if (haveA) {
            // cross-team tree reduce of col partials
            sA[t] = pai; sB[t] = pao;
            __syncthreads();
            if (t < 512) { f4add(sA[t], sA[t + 512]); f4add(sB[t], sB[t + 512]); }
            __syncthreads();
            if (t < 256) { f4add(sA[t], sA[t + 256]); f4add(sB[t], sB[t + 256]); }
            __syncthreads();
            const int slot = s & 1;
            if (t < 128) {
                float4 rai = sA[t]; f4add(rai, sA[t + 128]);
                float4 rao = sB[t]; f4add(rao, sB[t + 128]);
                *reinterpret_cast<float4*>(&g_part[slot][cta][t * 4])       = rai;
                *reinterpret_cast<float4*>(&g_part[slot][cta][512 + t * 4]) = rao;
            }
            __threadfence();
            __syncthreads();
            if (t == 0) {
                atomicAdd(&g_doneA[s], 1);
                while (ld_acq(&g_doneA[s]) < GRID) __nanosleep(32);
            }
            __syncthreads();

            // distributed finish: this CTA reduces its 1-2 float4 chunks of ai/ao[s]
            const int c_lo = (cta * 256) / GRID;
            const int c_hi = ((cta + 1) * 256) / GRID;
            const int wrp = t >> 5, l = t & 31;
            const int v = c_lo + wrp;
            if (v < c_hi) {
                float4 sum = make_float4(0.f, 0.f, 0.f, 0.f);
                for (int p = l; p < GRID; p += 32)
                    f4add(sum, *reinterpret_cast<const float4*>(&g_part[slot][p][v * 4]));
#pragma unroll
                for (int off = 16; off; off >>= 1) {
                    sum.x += __shfl_xor_sync(0xffffffffu, sum.x, off);
                    sum.y += __shfl_xor_sync(0xffffffffu, sum.y, off);
                    sum.z += __shfl_xor_sync(0xffffffffu, sum.z, off);
                    sum.w += __shfl_xor_sync(0xffffffffu, sum.w, off);
                }
                if (l == 0) {
                    const int which = v >> 7, cg = v & 127;
                    const float4 wv = *reinterpret_cast<const float4*>(ew + (size_t)s * W + cg * 4);
                    sum.x *= wv.x; sum.y *= wv.y; sum.z *= wv.z; sum.w *= wv.w;
                    if (which == 0)
                        *reinterpret_cast<float4*>(&g_ai[s * W + cg * 4]) = sum;
                    else
                        *reinterpret_cast<float4*>(&g_ao[s * W + cg * 4]) = sum;
                }
            }
            __threadfence();
            __syncthreads();
            if (t == 0) atomicAdd(&g_fin[s], 1);
        }
    }

    // final per-row reduction (128 lanes -> 1 scalar per row)
#pragma unroll
    for (int k = 0; k < KMAX; ++k) {
        const int rr = team + k * 8;
        float vsum = accB[k];
#pragma unroll
        for (int off = 16; off; off >>= 1)
            vsum += __shfl_down_sync(0xffffffffu, vsum, off);
        if ((t & 31) == 0) sred[team][(t >> 5) & 3] = vsum;
        __syncthreads();
        if (lane == 0 && rr < nrows)
            out[r0 + rr] = sred[team][0] + sred[team][1] + sred[team][2] + sred[team][3]
                         + g_c[r0 + rr];
        __syncthreads();
    }
}

extern "C" void kernel_launch(void* const* d_in, const int* in_sizes, int n_in,
                              void* d_out, int out_size) {
    const float* X    = (const float*)d_in[0];  // [N,4]
    const float* ew   = (const float*)d_in[1];  // [E,1]
    const float* Ri   = (const float*)d_in[2];  // [N,E]
    const float* Ro   = (const float*)d_in[3];  // [N,E]
    const float* kern = (const float*)d_in[4];  // [12,1]
    float* out = (float*)d_out;                 // [N,1]

    k1_prep<<<NN / 256, 256>>>(X, kern);
    fused<<<GRID, TPB>>>(Ri, Ro, ew, out);
}

// round 4
// speedup vs baseline: 1.3424x; 1.3424x over previous
#include <cuda_runtime.h>

#define NN 8192
#define NE 16384
#define W  512
#define NS (NE / W)          // 32 strips
#define NP 148               // producer CTAs (one per SM)
#define NC 148               // consumer CTAs (one per SM)
#define TPB 512
#define LEAD 2               // producer may run LEAD strips ahead
#define RMAXP 14             // ceil(56 rows / 4 subs)
#define KMAXC 14             // ceil(56 rows / 4 teams)

// ---- scratch (device globals; no allocation allowed) ----
__device__ float g_u[NN];
__device__ float g_v[NN];
__device__ float g_c[NN];
__device__ float g_ai[NE];
__device__ float g_ao[NE];
__device__ float g_part[2][NP][2 * W];   // [slot][prod][ai*512 | ao*512]
__device__ int   g_doneA[NS];            // producers finished strip s
__device__ int   g_fin[NS];              // consumers finished finish-reduce of s
__device__ int   g_cons[NS];             // consumers finished dot-reads of s

__device__ __forceinline__ int ld_acq(const int* p) {
    int v;
    asm volatile("ld.acquire.gpu.s32 %0, [%1];" : "=r"(v) : "l"(p) : "memory");
    return v;
}
__device__ __forceinline__ void f4add(float4& a, const float4 b) {
    a.x += b.x; a.y += b.y; a.z += b.z; a.w += b.w;
}
__device__ __forceinline__ void f4fma(float4& a, const float4 b, float s) {
    a.x += b.x * s; a.y += b.y * s; a.z += b.z * s; a.w += b.w * s;
}
__device__ __forceinline__ float4 ldcg4(const float* p) {
    float4 r;
    asm volatile("ld.global.cg.v4.f32 {%0,%1,%2,%3}, [%4];"
                 : "=f"(r.x), "=f"(r.y), "=f"(r.z), "=f"(r.w) : "l"(p));
    return r;
}

// Prep: per-node scalars u=X·k1, v=X·k2, c=X·k3; reset sync counters.
__global__ void k1_prep(const float* __restrict__ X, const float* __restrict__ kw) {
    int n = blockIdx.x * blockDim.x + threadIdx.x;
    if (n < NS) { g_doneA[n] = 0; g_fin[n] = 0; g_cons[n] = 0; }
    if (n >= NN) return;
    float4 x = reinterpret_cast<const float4*>(X)[n];
    g_u[n] = x.x * kw[0] + x.y * kw[1] + x.z * kw[2]  + x.w * kw[3];
    g_v[n] = x.x * kw[4] + x.y * kw[5] + x.z * kw[6]  + x.w * kw[7];
    g_c[n] = x.x * kw[8] + x.y * kw[9] + x.z * kw[10] + x.w * kw[11];
}

__global__ __launch_bounds__(TPB, 2) void fused(const float* __restrict__ Ri,
                                                const float* __restrict__ Ro,
                                                const float* __restrict__ ew,
                                                float* __restrict__ out) {
    __shared__ float4 sA[TPB];     // 8 KB
    __shared__ float4 sB[TPB];     // 8 KB
    __shared__ float  spu[56], spv[56];
    __shared__ float  sred[4][4];

    const int t   = threadIdx.x;
    const int cta = blockIdx.x;

    if (cta < NP) {
        // ========================= PRODUCER =========================
        const int p  = cta;
        const int r0 = (int)(((long long)p * NN) / NP);
        const int r1 = (int)(((long long)(p + 1) * NN) / NP);
        const int nrows = r1 - r0;
        const int lane = t & 127;       // float4 col group
        const int sub  = t >> 7;        // 0..3
        if (t < nrows) { spu[t] = g_u[r0 + t]; spv[t] = g_v[r0 + t]; }
        __syncthreads();

        for (int s = 0; s < NS; ++s) {
            // flow control: stay <= LEAD strips ahead of consumers (slot reuse + L2 footprint)
            if (s >= LEAD) {
                if (t == 0) { while (ld_acq(&g_cons[s - LEAD]) < NC) __nanosleep(64); }
                __syncthreads();
            }
            float4 pai = make_float4(0.f, 0.f, 0.f, 0.f);
            float4 pao = make_float4(0.f, 0.f, 0.f, 0.f);
            const size_t colA = (size_t)s * W + lane * 4;
#pragma unroll
            for (int k = 0; k < RMAXP; ++k) {
                const int rr = sub + k * 4;
                if (rr < nrows) {
                    const float4 a = *reinterpret_cast<const float4*>(Ri + (size_t)(r0 + rr) * NE + colA);
                    const float4 b = *reinterpret_cast<const float4*>(Ro + (size_t)(r0 + rr) * NE + colA);
                    f4fma(pai, b, spu[rr]);    // ai += Ro * u
                    f4fma(pao, a, spv[rr]);    // ao += Ri * v
                }
            }
            sA[t] = pai; sB[t] = pao;
            __syncthreads();
            if (t < 256) { f4add(sA[t], sA[t + 256]); f4add(sB[t], sB[t + 256]); }
            __syncthreads();
            if (t < 128) {
                float4 rai = sA[t]; f4add(rai, sA[t + 128]);
                float4 rao = sB[t]; f4add(rao, sB[t + 128]);
                const int slot = s & 1;
                *reinterpret_cast<float4*>(&g_part[slot][p][t * 4])       = rai;
                *reinterpret_cast<float4*>(&g_part[slot][p][W + t * 4])   = rao;
            }
            __threadfence();
            __syncthreads();
            if (t == 0) atomicAdd(&g_doneA[s], 1);
        }
    } else {
        // ========================= CONSUMER =========================
        const int c  = cta - NP;
        const int r0 = (int)(((long long)c * NN) / NC);
        const int r1 = (int)(((long long)(c + 1) * NN) / NC);
        const int nrows = r1 - r0;
        const int lane = t & 127;       // float4 col group
        const int team = t >> 7;        // 0..3

        float acc[KMAXC];
#pragma unroll
        for (int k = 0; k < KMAXC; ++k) acc[k] = 0.f;

        // this consumer's finish-reduce chunk(s): 256 float4 outputs over NC CTAs
        const int c_lo = (c * 256) / NC;
        const int c_hi = ((c + 1) * 256) / NC;
        const int wrp = t >> 5, l32 = t & 31;

        for (int s = 0; s < NS; ++s) {
            const int slot = s & 1;
            // wait for all producers on strip s
            if (t == 0) { while (ld_acq(&g_doneA[s]) < NP) __nanosleep(64); }
            __syncthreads();
            // distributed finish: reduce 148 partials for my chunk(s), scale by e
            const int v = c_lo + wrp;
            if (v < c_hi) {
                float4 sum = make_float4(0.f, 0.f, 0.f, 0.f);
                for (int pp = l32; pp < NP; pp += 32)
                    f4add(sum, ldcg4(&g_part[slot][pp][v * 4]));
#pragma unroll
                for (int off = 16; off; off >>= 1) {
                    sum.x += __shfl_xor_sync(0xffffffffu, sum.x, off);
                    sum.y += __shfl_xor_sync(0xffffffffu, sum.y, off);
                    sum.z += __shfl_xor_sync(0xffffffffu, sum.z, off);
                    sum.w += __shfl_xor_sync(0xffffffffu, sum.w, off);
                }
                if (l32 == 0) {
                    const int which = v >> 7, cg = v & 127;
                    const float4 wv = *reinterpret_cast<const float4*>(ew + (size_t)s * W + cg * 4);
                    sum.x *= wv.x; sum.y *= wv.y; sum.z *= wv.z; sum.w *= wv.w;
                    float* dst = (which == 0) ? &g_ai[s * W + cg * 4] : &g_ao[s * W + cg * 4];
                    *reinterpret_cast<float4*>(dst) = sum;
                }
            }
            __threadfence();
            __syncthreads();
            if (t == 0) {
                atomicAdd(&g_fin[s], 1);
                while (ld_acq(&g_fin[s]) < NC) __nanosleep(64);
            }
            __syncthreads();
            // row-dot over strip s (L2-resident), ai/ao via L2 loads
            const float4 vai = ldcg4(&g_ai[s * W + lane * 4]);
            const float4 vao = ldcg4(&g_ao[s * W + lane * 4]);
            const size_t colA = (size_t)s * W + lane * 4;
#pragma unroll
            for (int k = 0; k < KMAXC; ++k) {
                const int rr = team + k * 4;
                if (rr < nrows) {
                    const float4 a = ldcg4(Ri + (size_t)(r0 + rr) * NE + colA);
                    const float4 b = ldcg4(Ro + (size_t)(r0 + rr) * NE + colA);
                    acc[k] += a.x * vai.x + a.y * vai.y + a.z * vai.z + a.w * vai.w
                            + b.x * vao.x + b.y * vao.y + b.z * vao.z + b.w * vao.w;
                }
            }
            __syncthreads();
            if (t == 0) atomicAdd(&g_cons[s], 1);
        }

        // final per-row reduction: 128 lanes (4 warps) -> scalar
#pragma unroll
        for (int k = 0; k < KMAXC; ++k) {
            const int rr = team + k * 4;
            float vsum = acc[k];
#pragma unroll
            for (int off = 16; off; off >>= 1)
                vsum += __shfl_down_sync(0xffffffffu, vsum, off);
            if ((t & 31) == 0) sred[team][(t >> 5) & 3] = vsum;
            __syncthreads();
            if (lane == 0 && rr < nrows)
                out[r0 + rr] = sred[team][0] + sred[team][1] + sred[team][2] + sred[team][3]
                             + g_c[r0 + rr];
            __syncthreads();
        }
    }
}

extern "C" void kernel_launch(void* const* d_in, const int* in_sizes, int n_in,
                              void* d_out, int out_size) {
    const float* X    = (const float*)d_in[0];  // [N,4]
    const float* ew   = (const float*)d_in[1];  // [E,1]
    const float* Ri   = (const float*)d_in[2];  // [N,E]
    const float* Ro   = (const float*)d_in[3];  // [N,E]
    const float* kern = (const float*)d_in[4];  // [12,1]
    float* out = (float*)d_out;                 // [N,1]

    k1_prep<<<NN / 256, 256>>>(X, kern);
    fused<<<NP + NC, TPB>>>(Ri, Ro, ew, out);
}